// round 11
// baseline (speedup 1.0000x reference)
#include <cuda_runtime.h>
#include <cuda_bf16.h>
#include <cstdint>
#include <math.h>

// Problem constants
#define BATCH 2
#define SEQ   2048
#define CH    1024
#define NH    16
#define HD    64
#define C3    (3*CH)        // 3072
#define MROWS (BATCH*SEQ)   // 4096

// Scratch (allocation-guard safe: __device__ globals)
__device__ float g_qkv[(size_t)BATCH * SEQ * C3];   // [B,T,3C] tf32-rounded, natural cols
__device__ float g_y  [(size_t)BATCH * SEQ * CH];   // [B,T,C]  tf32-rounded, K-permuted cols
__device__ float g_xr [(size_t)BATCH * SEQ * CH];   // x, tf32-rounded, K-permuted cols
__device__ float g_wtq[(size_t)C3 * CH];            // w_qkv^T, tf32-rounded, K-permuted cols
__device__ float g_wto[(size_t)CH * CH];            // w_out^T, tf32-rounded, K-permuted cols

// K-permutation within each 32-chunk: pos(k) = (k&3)*8 + (k>>2); inv(p) = (p&7)*4 + (p>>3)

// ---------------------------------------------------------------------------
// Helpers
// ---------------------------------------------------------------------------
__device__ __forceinline__ float to_tf32(float x) {
    float r; asm("cvt.rna.tf32.f32 %0, %1;" : "=f"(r) : "f"(x)); return r;
}
__device__ __forceinline__ uint32_t fbits(float x) { return __float_as_uint(x); }

__device__ __forceinline__ uint32_t smem_u32(const void* p) {
    uint32_t a;
    asm("{ .reg .u64 t; cvta.to.shared.u64 t, %1; cvt.u32.u64 %0, t; }" : "=r"(a) : "l"(p));
    return a;
}
__device__ __forceinline__ void cp16(uint32_t s, const void* g) {
    asm volatile("cp.async.cg.shared.global [%0], [%1], 16;" :: "r"(s), "l"(g));
}

// m16n8k8 tf32 MMA, D += A*B
__device__ __forceinline__ void mma_tf32(float* d,
                                         uint32_t a0, uint32_t a1, uint32_t a2, uint32_t a3,
                                         uint32_t b0, uint32_t b1) {
    asm volatile(
        "mma.sync.aligned.m16n8k8.row.col.f32.tf32.tf32.f32 "
        "{%0,%1,%2,%3}, {%4,%5,%6,%7}, {%8,%9}, {%0,%1,%2,%3};"
        : "+f"(d[0]), "+f"(d[1]), "+f"(d[2]), "+f"(d[3])
        : "r"(a0), "r"(a1), "r"(a2), "r"(a3), "r"(b0), "r"(b1));
}

// ---------------------------------------------------------------------------
// Round to tf32 + K-permute within 32-chunks (for x). Smem-staged, coalesced.
// Block handles 8192 contiguous floats.
// ---------------------------------------------------------------------------
__global__ __launch_bounds__(256)
void round_perm_kernel(const float* __restrict__ in, float* __restrict__ out)
{
    __shared__ float s[8192];
    size_t base = (size_t)blockIdx.x * 8192;
#pragma unroll
    for (int j = 0; j < 8; j++) {
        int q = j * 1024 + threadIdx.x * 4;
        *(float4*)&s[q] = *(const float4*)(in + base + q);
    }
    __syncthreads();
#pragma unroll
    for (int j = 0; j < 8; j++) {
        int q = j * 1024 + threadIdx.x * 4;
        float4 o;
        {
            int p = q + 0, lp = p & 31; o.x = to_tf32(s[(p & ~31) + ((lp & 7) * 4 + (lp >> 3))]);
        }
        {
            int p = q + 1, lp = p & 31; o.y = to_tf32(s[(p & ~31) + ((lp & 7) * 4 + (lp >> 3))]);
        }
        {
            int p = q + 2, lp = p & 31; o.z = to_tf32(s[(p & ~31) + ((lp & 7) * 4 + (lp >> 3))]);
        }
        {
            int p = q + 3, lp = p & 31; o.w = to_tf32(s[(p & ~31) + ((lp & 7) * 4 + (lp >> 3))]);
        }
        *(float4*)(out + base + q) = o;
    }
}

// ---------------------------------------------------------------------------
// Transpose + tf32-round + K-permute: out[c][perm(r)] = tf32(in[r][c])
// Implemented as coalesced write with permuted smem gather.
// ---------------------------------------------------------------------------
__global__ __launch_bounds__(256, 8)
void transpose_round_kernel(const float* __restrict__ in, float* __restrict__ out, int R, int C)
{
    __shared__ float t[32][33];
    int tx = threadIdx.x, ty = threadIdx.y;     // 32 x 8
    int c0 = blockIdx.x * 32, r0 = blockIdx.y * 32;
#pragma unroll
    for (int k = 0; k < 4; k++)
        t[ty + 8 * k][tx] = in[(size_t)(r0 + ty + 8 * k) * C + c0 + tx];
    __syncthreads();
    const int inv_tx = (tx & 7) * 4 + (tx >> 3);   // orig k whose permuted slot is tx
#pragma unroll
    for (int k = 0; k < 4; k++)
        out[(size_t)(c0 + ty + 8 * k) * R + r0 + tx] = to_tf32(t[inv_tx][ty + 8 * k]);
}

// ---------------------------------------------------------------------------
// TF32 mma.sync GEMM: C[M,N] = A[M,K] @ Bt[N,K]^T + bias[N]
// A, Bt have K-permuted columns (32-chunk granularity).
// CTA 128x128, 8 warps (warp tile 64x32), KC=32, 3-stage cp.async.
// Fragments for the whole chunk loaded via LDS.128 (2 per row), then MMA burst.
// ---------------------------------------------------------------------------
#define GKC 32
#define GSTR 36
#define GTILE (128 * GSTR)                   // floats per buffer (18432 B)
#define GSTAGES 3
#define G_SMEM (2 * GSTAGES * GTILE * 4)     // 110592 B

template<bool RND>
__global__ __launch_bounds__(256, 1)
void gemm_mma_kernel(int M, int N, int K,
                     const float* __restrict__ A,
                     const float* __restrict__ Bt,
                     const float* __restrict__ bias,
                     float* __restrict__ C)
{
    extern __shared__ float smg[];
    const uint32_t smem_base = smem_u32(smg);

    const int tid = threadIdx.x;
    const int lane = tid & 31, wid = tid >> 5;   // 8 warps: 2(m) x 4(n)
    const int n0 = blockIdx.x * 128;
    const int m0 = blockIdx.y * 128;
    const int mb = (wid & 1) * 64;
    const int nb = (wid >> 1) * 32;

    float acc[4][4][4];
#pragma unroll
    for (int mt = 0; mt < 4; mt++)
#pragma unroll
        for (int nt = 0; nt < 4; nt++)
#pragma unroll
            for (int r = 0; r < 4; r++) acc[mt][nt][r] = 0.f;

    const int lr = tid >> 3;            // 0..31
    const int lc4 = (tid & 7) * 4;      // 0..28

    const int nch = K / GKC;

    auto issue = [&](int buf, int kb) {
        uint32_t a_s = smem_base + (uint32_t)buf * GTILE * 4;
        uint32_t b_s = smem_base + (uint32_t)(GSTAGES + buf) * GTILE * 4;
#pragma unroll
        for (int p = 0; p < 4; p++) {
            int r = lr + p * 32;
            cp16(a_s + (uint32_t)(r * GSTR + lc4) * 4, A  + (size_t)(m0 + r) * K + kb + lc4);
            cp16(b_s + (uint32_t)(r * GSTR + lc4) * 4, Bt + (size_t)(n0 + r) * K + kb + lc4);
        }
        asm volatile("cp.async.commit_group;");
    };

    issue(0, 0);
    if (nch > 1) issue(1, GKC);

    const int fcol = (lane & 3) * 8;      // this thread's 8-float fragment column
    const int frow = lane >> 2;           // fragment row within 16-row tile

    for (int c = 0; c < nch; c++) {
        if (c + 1 < nch) asm volatile("cp.async.wait_group 1;");
        else             asm volatile("cp.async.wait_group 0;");
        __syncthreads();
        if (c + 2 < nch) issue((c + 2) % GSTAGES, (c + 2) * GKC);

        const float* Ab = smg + (c % GSTAGES) * GTILE;
        const float* Bb = smg + (GSTAGES + (c % GSTAGES)) * GTILE;

        // Load ALL fragments for this chunk: a8[mt][rowhalf][j], j -> k = 4j + (lane&3)
        float a8[4][2][8];
        float b8[4][8];
#pragma unroll
        for (int mt = 0; mt < 4; mt++) {
            const float* pa = Ab + (mb + mt * 16 + frow) * GSTR + fcol;
            *(float4*)&a8[mt][0][0] = *(const float4*)(pa);
            *(float4*)&a8[mt][0][4] = *(const float4*)(pa + 4);
            *(float4*)&a8[mt][1][0] = *(const float4*)(pa + 8 * GSTR);
            *(float4*)&a8[mt][1][4] = *(const float4*)(pa + 8 * GSTR + 4);
        }
#pragma unroll
        for (int nt = 0; nt < 4; nt++) {
            const float* pb = Bb + (nb + nt * 8 + frow) * GSTR + fcol;
            *(float4*)&b8[nt][0] = *(const float4*)(pb);
            *(float4*)&b8[nt][4] = *(const float4*)(pb + 4);
        }

        // MMA burst: 4 k-steps x 4 nt x 4 mt
#pragma unroll
        for (int g = 0; g < 4; g++) {
#pragma unroll
            for (int nt = 0; nt < 4; nt++) {
                uint32_t b0 = fbits(b8[nt][2 * g]), b1 = fbits(b8[nt][2 * g + 1]);
#pragma unroll
                for (int mt = 0; mt < 4; mt++)
                    mma_tf32(acc[mt][nt],
                             fbits(a8[mt][0][2 * g]),     fbits(a8[mt][1][2 * g]),
                             fbits(a8[mt][0][2 * g + 1]), fbits(a8[mt][1][2 * g + 1]),
                             b0, b1);
            }
        }
    }

    // epilogue
#pragma unroll
    for (int mt = 0; mt < 4; mt++) {
        const int row0 = m0 + mb + mt * 16 + frow;
#pragma unroll
        for (int nt = 0; nt < 4; nt++) {
            const int col = n0 + nb + nt * 8 + (lane & 3) * 2;
            float bv0 = __ldg(bias + col), bv1 = __ldg(bias + col + 1);
            float2 o0 = { acc[mt][nt][0] + bv0, acc[mt][nt][1] + bv1 };
            float2 o1 = { acc[mt][nt][2] + bv0, acc[mt][nt][3] + bv1 };
            if (RND) {
                o0.x = to_tf32(o0.x); o0.y = to_tf32(o0.y);
                o1.x = to_tf32(o1.x); o1.y = to_tf32(o1.y);
            }
            *(float2*)(C + (size_t)row0 * N + col)       = o0;
            *(float2*)(C + (size_t)(row0 + 8) * N + col) = o1;
        }
    }
}

// ---------------------------------------------------------------------------
// Flash attention, tf32 mma.sync, causal (unchanged from R6 except the
// epilogue, which stores y with K-permuted channel positions for the
// out-projection GEMM).
// ---------------------------------------------------------------------------
#define ASTR 68
#define AVSTR 72
#define A_OFF_Q 0
#define A_OFF_K0 8704
#define A_OFF_K1 13056
#define A_OFF_V0 17408
#define A_OFF_V1 22016
#define A_OFF_P  26624
#define ATT_SMEM (35328 * 4)   // 141312 B

__global__ __launch_bounds__(256, 1)
void flash_mma_kernel(const float* __restrict__ qkv, float* __restrict__ y)
{
    extern __shared__ float smf[];
    const uint32_t smem_base = smem_u32(smf);

    const int tid = threadIdx.x;
    const int lane = tid & 31, wid = tid >> 5;       // 8 warps
    const int qt = (int)gridDim.x - 1 - (int)blockIdx.x;  // big CTAs first
    const int h  = blockIdx.y;
    const int b  = blockIdx.z;
    const int q0 = qt * 128;

    const float* qb = qkv + ((size_t)(b * SEQ + q0)) * C3 + h * HD;
    const float* kb = qkv + ((size_t)(b * SEQ)) * C3 + CH + h * HD;
    const float* vb = kb + CH;

    const int kofs[2] = { A_OFF_K0, A_OFF_K1 };
    const int vofs[2] = { A_OFF_V0, A_OFF_V1 };

    auto issue_kv = [&](int buf, int kt) {
#pragma unroll
        for (int p = 0; p < 4; p++) {
            int idx = tid + p * 256;
            int row = idx >> 4, c4 = (idx & 15) * 4;
            size_t g = (size_t)(kt * 64 + row) * C3 + c4;
            cp16(smem_base + (uint32_t)(kofs[buf] + row * ASTR  + c4) * 4, kb + g);
            cp16(smem_base + (uint32_t)(vofs[buf] + row * AVSTR + c4) * 4, vb + g);
        }
        asm volatile("cp.async.commit_group;");
    };

    // prologue: Q (128x64) + K/V tile 0
#pragma unroll
    for (int p = 0; p < 8; p++) {
        int idx = tid + p * 256;
        int row = idx >> 4, c4 = (idx & 15) * 4;
        cp16(smem_base + (uint32_t)(A_OFF_Q + row * ASTR + c4) * 4,
             qb + (size_t)row * C3 + c4);
    }
    issue_kv(0, 0);

    float m0r = -1e30f, m1r = -1e30f, l0 = 0.f, l1 = 0.f;
    float oacc[8][4];
#pragma unroll
    for (int nt = 0; nt < 8; nt++)
#pragma unroll
        for (int r = 0; r < 4; r++) oacc[nt][r] = 0.f;

    const int qrow = 16 * wid + (lane >> 2);
    const int rg0 = q0 + qrow, rg1 = rg0 + 8;
    const float* Qs = smf + A_OFF_Q;
    float* Ps = smf + A_OFF_P;

    const int ktmax = 2 * qt + 2;
    for (int kt = 0; kt < ktmax; kt++) {
        asm volatile("cp.async.wait_group 0;");
        __syncthreads();
        if (kt + 1 < ktmax) issue_kv((kt + 1) & 1, kt + 1);

        const float* Ks = smf + kofs[kt & 1];
        const float* Vs = smf + vofs[kt & 1];

        // S = Q @ K^T
        float sacc[8][4];
#pragma unroll
        for (int nt = 0; nt < 8; nt++)
#pragma unroll
            for (int r = 0; r < 4; r++) sacc[nt][r] = 0.f;

#pragma unroll
        for (int k = 0; k < 8; k++) {
            const int kk = k * 8;
            const float* pa = &Qs[qrow * ASTR + kk + (lane & 3)];
            uint32_t a0 = fbits(pa[0]), a1 = fbits(pa[8 * ASTR]);
            uint32_t a2 = fbits(pa[4]), a3 = fbits(pa[8 * ASTR + 4]);
#pragma unroll
            for (int nt = 0; nt < 8; nt++) {
                const float* pb = &Ks[(nt * 8 + (lane >> 2)) * ASTR + kk + (lane & 3)];
                mma_tf32(sacc[nt], a0, a1, a2, a3, fbits(pb[0]), fbits(pb[4]));
            }
        }

        const float scale = 0.125f;
#pragma unroll
        for (int nt = 0; nt < 8; nt++)
#pragma unroll
            for (int r = 0; r < 4; r++) sacc[nt][r] *= scale;

        if (kt >= 2 * qt) {
#pragma unroll
            for (int nt = 0; nt < 8; nt++) {
                int cg = kt * 64 + nt * 8 + (lane & 3) * 2;
                if (cg     > rg0) sacc[nt][0] = -1e30f;
                if (cg + 1 > rg0) sacc[nt][1] = -1e30f;
                if (cg     > rg1) sacc[nt][2] = -1e30f;
                if (cg + 1 > rg1) sacc[nt][3] = -1e30f;
            }
        }

        // online softmax
        float mx0 = -1e30f, mx1 = -1e30f;
#pragma unroll
        for (int nt = 0; nt < 8; nt++) {
            mx0 = fmaxf(mx0, fmaxf(sacc[nt][0], sacc[nt][1]));
            mx1 = fmaxf(mx1, fmaxf(sacc[nt][2], sacc[nt][3]));
        }
        mx0 = fmaxf(mx0, __shfl_xor_sync(0xffffffffu, mx0, 1));
        mx0 = fmaxf(mx0, __shfl_xor_sync(0xffffffffu, mx0, 2));
        mx1 = fmaxf(mx1, __shfl_xor_sync(0xffffffffu, mx1, 1));
        mx1 = fmaxf(mx1, __shfl_xor_sync(0xffffffffu, mx1, 2));

        float mn0 = fmaxf(m0r, mx0), mn1 = fmaxf(m1r, mx1);
        float fac0 = __expf(m0r - mn0), fac1 = __expf(m1r - mn1);
        m0r = mn0; m1r = mn1;

        float rs0 = 0.f, rs1 = 0.f;
#pragma unroll
        for (int nt = 0; nt < 8; nt++) {
            sacc[nt][0] = __expf(sacc[nt][0] - mn0);
            sacc[nt][1] = __expf(sacc[nt][1] - mn0);
            sacc[nt][2] = __expf(sacc[nt][2] - mn1);
            sacc[nt][3] = __expf(sacc[nt][3] - mn1);
            rs0 += sacc[nt][0] + sacc[nt][1];
            rs1 += sacc[nt][2] + sacc[nt][3];
        }
        rs0 += __shfl_xor_sync(0xffffffffu, rs0, 1);
        rs0 += __shfl_xor_sync(0xffffffffu, rs0, 2);
        rs1 += __shfl_xor_sync(0xffffffffu, rs1, 1);
        rs1 += __shfl_xor_sync(0xffffffffu, rs1, 2);

        l0 = l0 * fac0 + rs0;
        l1 = l1 * fac1 + rs1;
#pragma unroll
        for (int nt = 0; nt < 8; nt++) {
            oacc[nt][0] *= fac0; oacc[nt][1] *= fac0;
            oacc[nt][2] *= fac1; oacc[nt][3] *= fac1;
        }

        // stage P (tf32-rounded)
#pragma unroll
        for (int nt = 0; nt < 8; nt++) {
            int c = nt * 8 + (lane & 3) * 2;
            float2 p0 = { to_tf32(sacc[nt][0]), to_tf32(sacc[nt][1]) };
            float2 p1 = { to_tf32(sacc[nt][2]), to_tf32(sacc[nt][3]) };
            *(float2*)&Ps[qrow * ASTR + c]       = p0;
            *(float2*)&Ps[(qrow + 8) * ASTR + c] = p1;
        }
        __syncwarp();

        // O += P @ V
#pragma unroll
        for (int k = 0; k < 8; k++) {
            const int kk = k * 8;
            const float* pa = &Ps[qrow * ASTR + kk + (lane & 3)];
            uint32_t a0 = fbits(pa[0]), a1 = fbits(pa[8 * ASTR]);
            uint32_t a2 = fbits(pa[4]), a3 = fbits(pa[8 * ASTR + 4]);
#pragma unroll
            for (int nt = 0; nt < 8; nt++) {
                uint32_t b0 = fbits(Vs[(kk +     (lane & 3)) * AVSTR + nt * 8 + (lane >> 2)]);
                uint32_t b1 = fbits(Vs[(kk + 4 + (lane & 3)) * AVSTR + nt * 8 + (lane >> 2)]);
                mma_tf32(oacc[nt], a0, a1, a2, a3, b0, b1);
            }
        }
    }

    // epilogue: divide by l, tf32-round, store with K-permuted channel layout
    float inv0 = 1.f / l0, inv1 = 1.f / l1;
    float* y0 = y + ((size_t)(b * SEQ + rg0)) * CH + h * HD;
    float* y1 = y0 + 8 * CH;
#pragma unroll
    for (int nt = 0; nt < 8; nt++) {
        int c = nt * 8 + (lane & 3) * 2;       // cols c, c+1 in [0,64)
#pragma unroll
        for (int e = 0; e < 2; e++) {
            int cc = c + e;
            int pc = (cc & 32) | ((cc & 3) * 8 + ((cc & 31) >> 2));
            y0[pc] = to_tf32(oacc[nt][e]     * inv0);
            y1[pc] = to_tf32(oacc[nt][2 + e] * inv1);
        }
    }
}

// ---------------------------------------------------------------------------
extern "C" void kernel_launch(void* const* d_in, const int* in_sizes, int n_in,
                              void* d_out, int out_size)
{
    const float* x     = (const float*)d_in[0];
    const float* w_qkv = (const float*)d_in[1];
    const float* b_qkv = (const float*)d_in[2];
    const float* w_out = (const float*)d_in[3];
    const float* b_out = (const float*)d_in[4];
    float* out = (float*)d_out;

    float* qkv; cudaGetSymbolAddress((void**)&qkv, g_qkv);
    float* y;   cudaGetSymbolAddress((void**)&y,   g_y);
    float* xr;  cudaGetSymbolAddress((void**)&xr,  g_xr);
    float* wtq; cudaGetSymbolAddress((void**)&wtq, g_wtq);
    float* wto; cudaGetSymbolAddress((void**)&wto, g_wto);

    static bool attr_set = false;
    if (!attr_set) {
        cudaFuncSetAttribute(gemm_mma_kernel<true>,
                             cudaFuncAttributeMaxDynamicSharedMemorySize, G_SMEM);
        cudaFuncSetAttribute(gemm_mma_kernel<false>,
                             cudaFuncAttributeMaxDynamicSharedMemorySize, G_SMEM);
        cudaFuncSetAttribute(flash_mma_kernel,
                             cudaFuncAttributeMaxDynamicSharedMemorySize, ATT_SMEM);
        attr_set = true;
    }

    // 0) precondition operands: tf32 round + K-permute
    round_perm_kernel<<<(MROWS * CH) / 8192, 256>>>(x, xr);
    {
        dim3 blk(32, 8);
        transpose_round_kernel<<<dim3(C3 / 32, CH / 32), blk>>>(w_qkv, wtq, CH, C3);
        transpose_round_kernel<<<dim3(CH / 32, CH / 32), blk>>>(w_out, wto, CH, CH);
    }
    // 1) QKV projection (output tf32-rounded, natural col order)
    {
        dim3 grid(C3 / 128, MROWS / 128);
        gemm_mma_kernel<true><<<grid, 256, G_SMEM>>>(MROWS, C3, CH, xr, wtq, b_qkv, qkv);
    }
    // 2) causal flash attention -> y (tf32-rounded, K-permuted channels)
    {
        dim3 grid(SEQ / 128, NH, BATCH);
        flash_mma_kernel<<<grid, 256, ATT_SMEM>>>(qkv, y);
    }
    // 3) output projection (fp32 output, natural order)
    {
        dim3 grid(CH / 128, MROWS / 128);
        gemm_mma_kernel<false><<<grid, 128 + 128, G_SMEM>>>(MROWS, CH, CH, y, wto, b_out, out);
    }
}